// round 14
// baseline (speedup 1.0000x reference)
#include <cuda_runtime.h>
#include <math.h>
#include <stdint.h>

#define U1MAXc 221.519f
#define MLc    2.9086f
#define SLc    1.898f
#define SPINc  365
#define TRAINc 80000
#define GUc    32

#define NCHUNK 16384
#define WARMUP 48
#define CPB    128             // threads per block (= chunks per scan block)
#define LMAXc  8               // supports N up to NCHUNK*LMAXc = 131072
#define NSTD   16              // redundant std blocks appended to the grid

__device__ __forceinline__ float sigf(float x) {
    return 1.0f / (1.0f + __expf(-x));
}

__device__ __forceinline__ uint32_t smem_u32(const void* p) {
    uint32_t a;
    asm("{ .reg .u64 t; cvta.to.shared.u64 t, %1; cvt.u32.u64 %0, t; }"
        : "=r"(a) : "l"(p));
    return a;
}

// ---------------------------------------------------------------------------
// ONE kernel, grid = gridB + NSTD blocks, 128 threads, single wave.
//
//  Scan blocks [0, gridB): window of x bulk-copied to smem (one cp.async.bulk,
//    16B-aligned since tbase even), phase-1 precompute {g, ol, u2} smem->smem
//    with full ILP + direct c-independent outputs, chunk-parallel scan
//    (48 warmup + L=7 main; f = 1-oo-olc <= 0.943, empirically ~0.7 =>
//    seam error below float ulp at 48 — validated 512..48), vectorized flush.
//    Never touches obs.
//  Std blocks [gridB, gridB+NSTD): each redundantly computes
//    std(y_obs[SPIN:TRAIN], ddof=1) (fp32 ILP -> fp64 fold; validated R12)
//    and writes its 1/NSTD share of obs_std + h_nout[:,1].
//
// out layout (floats): h(0) c(N) l(2N) lc(3N) bp(4N) gib(5N) goo(6N) gol(7N)
//                      golc(8N) gf(9N) bc(10N) hnout(11N..13N) obs(13N)
// ---------------------------------------------------------------------------
__global__ void __launch_bounds__(CPB, 1)
kOne(const float2* __restrict__ x, const float* __restrict__ y,
     const float* __restrict__ cm, const float* __restrict__ cs,
     const float* __restrict__ wo, const float* __restrict__ wl,
     const float* __restrict__ wf,
     const float* __restrict__ b0o, const float* __restrict__ w1o,
     const float* __restrict__ b0l, const float* __restrict__ w2l,
     const float* __restrict__ ln_wj, const float* __restrict__ relu_bj,
     float* __restrict__ out, int N, int nY, int L, int gridB)
{
    __shared__ alignas(16) float4 s_in[CPB * LMAXc + WARMUP];  // 17152 B
    __shared__ alignas(16) float  s_st[7][CPB * LMAXc];        // 28672 B (aliased as s_x early)
    __shared__ float  s_bj[GUc], s_w[GUc];
    __shared__ double s_red[8];
    __shared__ alignas(8) uint64_t s_mbar;

    int tid  = threadIdx.x;
    int lane = tid & 31;
    int wid  = tid >> 5;

    // ======================= STD BLOCKS =======================
    if ((int)blockIdx.x >= gridB) {
        int sb = (int)blockIdx.x - gridB;
        int lo = SPINc;
        int hi = (TRAINc < nY) ? TRAINc : nY;

        float a0 = 0.f, a1 = 0.f, a2 = 0.f, a3 = 0.f;
        float q0 = 0.f, q1 = 0.f, q2 = 0.f, q3 = 0.f;
        int i = lo + tid;
        for (; i + 3 * CPB < hi; i += 4 * CPB) {
            float v0 = y[i];
            float v1 = y[i + CPB];
            float v2 = y[i + 2 * CPB];
            float v3 = y[i + 3 * CPB];
            a0 += v0; q0 = fmaf(v0, v0, q0);
            a1 += v1; q1 = fmaf(v1, v1, q1);
            a2 += v2; q2 = fmaf(v2, v2, q2);
            a3 += v3; q3 = fmaf(v3, v3, q3);
        }
        for (; i < hi; i += CPB) {
            float v = y[i];
            a0 += v; q0 = fmaf(v, v, q0);
        }
        double S = (double)a0 + (double)a1 + (double)a2 + (double)a3;
        double Q = (double)q0 + (double)q1 + (double)q2 + (double)q3;
#pragma unroll
        for (int o = 16; o > 0; o >>= 1) {
            S += __shfl_down_sync(0xffffffffu, S, o);
            Q += __shfl_down_sync(0xffffffffu, Q, o);
        }
        if (lane == 0) { s_red[wid] = S; s_red[4 + wid] = Q; }
        __syncthreads();
        double St = s_red[0] + s_red[1] + s_red[2] + s_red[3];
        double Qt = s_red[4] + s_red[5] + s_red[6] + s_red[7];
        double nn = (double)(hi - lo);
        float obs = (float)sqrt((Qt - St * St / nn) / (nn - 1.0));

        int chunk = (N + NSTD - 1) / NSTD;
        int w0 = sb * chunk;
        int w1 = w0 + chunk; if (w1 > N) w1 = N;
        // obs_std row (contiguous -> vectorize where aligned)
        int span = w1 - w0;
        float* dst = out + 13 * N + w0;
        int v0n = ((16 - (((uintptr_t)dst >> 2) & 3)) & 3);  // floats to align
        if (v0n > span) v0n = span;
        for (int t = tid; t < v0n; t += CPB) dst[t] = obs;
        int rem = span - v0n;
        float4* dv = (float4*)(dst + v0n);
        float4 ov = make_float4(obs, obs, obs, obs);
        for (int t4 = tid; t4 < (rem >> 2); t4 += CPB) dv[t4] = ov;
        for (int t = v0n + ((rem >> 2) << 2) + tid; t < span; t += CPB) dst[t] = obs;
        // h_nout[:,1] (stride-2 scalar)
        for (int t = w0 + tid; t < w1; t += CPB)
            out[11 * N + 2 * t + 1] = obs;
        return;
    }

    // ======================= SCAN BLOCKS =======================
    int m0    = blockIdx.x * CPB;
    int tbase = m0 * L;
    if (tbase >= N) return;
    int endT  = (m0 + CPB) * L; if (endT > N) endT = N;
    int baseT = tbase - WARMUP;              // may be negative (block 0)
    int base0 = (baseT > 0) ? baseT : 0;
    int lead  = base0 - baseT;               // leading zero elements in window
    int nWin  = endT - baseT;
    int nElem = endT - base0;

    float2* s_x = (float2*)&s_st[0][0];      // alias: x window staging

    uint32_t mbar = smem_u32(&s_mbar);
    if (tid == 0)
        asm volatile("mbarrier.init.shared.b64 [%0], 1;" :: "r"(mbar) : "memory");
    if (tid < GUc) {
        s_bj[tid] = fmaxf(relu_bj[tid], 0.0f);
        s_w[tid]  = ln_wj[tid];
    }
    __syncthreads();

    // ---- bulk async copy of the x window (float2; 16B-aligned: base0 even)
    int nBulk = nElem & ~1;                  // even count -> nbytes % 16 == 0
    if (tid == 0) {
        uint32_t dst    = smem_u32(&s_x[0]);
        uint32_t nbytes = (uint32_t)nBulk * 8u;
        asm volatile("mbarrier.arrive.expect_tx.shared.b64 _, [%0], %1;"
                     :: "r"(mbar), "r"(nbytes) : "memory");
        asm volatile("cp.async.bulk.shared::cta.global.mbarrier::complete_tx::bytes"
                     " [%0], [%1], %2, [%3];"
                     :: "r"(dst), "l"(&x[base0]), "r"(nbytes), "r"(mbar)
                     : "memory");
    }

    // ---- overlap: scalar params (broadcast loads) while copy flies
    float eo = __expf(wo[0]), elv = __expf(wl[0]), ef = __expf(wf[0]);
    float rd  = 1.0f / (eo + elv + ef);
    float oo1 = eo * rd;
    float ol1 = elv * rd;
    float w2  = w2l[0], b0 = b0l[0];
    float Aoo = w1o[0] / cs[0];
    float Boo = b0o[0] - cm[0] * Aoo;
    float At = 0.5f * Aoo, Bt = 0.5f * Boo;
    float noo1h = -0.5f * oo1;

    // ---- wait (acquire)
    {
        uint32_t done;
        asm volatile(
            "{\n\t.reg .pred p;\n\t"
            "mbarrier.try_wait.parity.acquire.cta.shared::cta.b64 p, [%1], %2;\n\t"
            "selp.b32 %0, 1, 0, p;\n\t}"
            : "=r"(done) : "r"(mbar), "r"(0) : "memory");
        while (!done) {
            asm volatile(
                "{\n\t.reg .pred p;\n\t"
                "mbarrier.try_wait.parity.acquire.cta.shared::cta.b64 p, [%1], %2, 0x989680;\n\t"
                "selp.b32 %0, 1, 0, p;\n\t}"
                : "=r"(done) : "r"(mbar), "r"(0) : "memory");
        }
    }
    if (nBulk < nElem && tid == 0)           // odd tail (N odd): one LDG
        s_x[nBulk] = x[base0 + nBulk];
    __syncthreads();

    // ---- phase 1: precompute window smem->smem (full ILP across elements)
    for (int i = tid; i < nWin; i += CPB) {
        int t = baseT + i;
        float4 v = make_float4(0.f, 0.f, 0.f, 0.f);
        if (t >= 0) {
            float2 xv = s_x[i - lead];
            float u1 = xv.x, u2v = xv.y;
            float u1r = u1 * (1.0f / U1MAXc);
            float d0 = 0.f, d1 = 0.f, d2 = 0.f, d3 = 0.f;
#pragma unroll
            for (int j = 0; j < GUc; j += 4) {
                d0 = fmaf(fmaxf(u1r - s_bj[j],     0.0f), s_w[j],     d0);
                d1 = fmaf(fmaxf(u1r - s_bj[j + 1], 0.0f), s_w[j + 1], d1);
                d2 = fmaf(fmaxf(u1r - s_bj[j + 2], 0.0f), s_w[j + 2], d2);
                d3 = fmaf(fmaxf(u1r - s_bj[j + 3], 0.0f), s_w[j + 3], d3);
            }
            float bc  = (d0 + d1) + (d2 + d3);
            float g   = fmaf(bc, U1MAXc, u1);
            float ol3 = fmaf((u2v - MLc) * (1.0f / SLc), w2, b0);
            float ol  = ol1 * sigf(ol3);
            v = make_float4(g, ol, u2v, 0.0f);
            if (t >= tbase) {                 // own span: direct outputs
                out[10 * N + t] = bc;         // BC_n
                out[7  * N + t] = ol;         // Gate_ol
                out[4  * N + t] = 0.0f;       // bp_n
                out[5  * N + t] = 0.0f;       // Gate_ib
            }
        }
        s_in[i] = v;
    }
    __syncthreads();                          // s_in ready; s_x dead -> s_st reusable

#define STEPP(P)                                                            \
    {                                                                       \
        float arg = fmaf(At, c, Bt);                                        \
        float tt;                                                           \
        asm("tanh.approx.f32 %0, %1;" : "=f"(tt) : "f"(arg));               \
        float qn = noo1h * c;                                               \
        float ss = c + (P).x;                                               \
        float lc = fminf((P).y * c, (P).z);                                 \
        float rr = (ss - lc) + qn;                                          \
        c = fmaf(qn, tt, rr);                                               \
    }

    // ---- phase 2: scan (zeros below t=0 keep c = 0 exactly)
    int sT = (m0 + tid) * L;
    if (sT < N) {
        int e = sT + L; if (e > N) e = N;
        int j = tid * L;                      // = (sT - WARMUP) - baseT
        float c = 0.0f;
#pragma unroll 4
        for (int k = 0; k < WARMUP; ++k, ++j) {
            float4 p = s_in[j];
            STEPP(p);
        }
        int li = tid * L;
        for (int t = sT; t < e; ++t, ++j) {
            float4 p = s_in[j];
            float c0 = c;
            float oo  = oo1 * sigf(fmaf(Aoo, c0, Boo));
            float ol  = p.y, u2v = p.z;
            float l0  = ol * c0;
            bool  pos = (c0 > 0.0f);
            float lcn = pos ? fminf(l0, u2v) : l0;
            float olc = pos ? fminf(ol, __fdividef(u2v, c0)) : ol;
            int k = li + (t - sT);
            s_st[0][k] = oo * c0;
            s_st[1][k] = c0;
            s_st[2][k] = l0;
            s_st[3][k] = lcn;
            s_st[4][k] = oo;
            s_st[5][k] = olc;
            s_st[6][k] = 1.0f - oo - olc;
            STEPP(p);
        }
    }
#undef STEPP
    __syncthreads();

    // ---- phase 3: vectorized coalesced flush (no obs rows here)
    int span  = endT - tbase;
    int span4 = span & ~3;
    const int offs[7] = {0, 1, 2, 3, 6, 8, 9};
#pragma unroll
    for (int k = 0; k < 7; ++k) {
        const float4* src = (const float4*)&s_st[k][0];
        float4* dstv = (float4*)(out + offs[k] * N + tbase);   // 16B-aligned
        for (int i4 = tid; i4 < (span4 >> 2); i4 += CPB)
            dstv[i4] = src[i4];
        for (int i = span4 + tid; i < span; i += CPB)
            out[offs[k] * N + tbase + i] = s_st[k][i];
    }
    for (int i = tid; i < span; i += CPB)     // h_nout[:,0] (stride-2)
        out[11 * N + 2 * (tbase + i)] = s_st[0][i];
}

// ---------------------------------------------------------------------------
extern "C" void kernel_launch(void* const* d_in, const int* in_sizes, int n_in,
                              void* d_out, int out_size)
{
    const float* x      = (const float*)d_in[0];
    // d_in[1] = epoch, d_in[2] = time_lag (unused)
    const float* y_obs  = (const float*)d_in[3];
    const float* cmean  = (const float*)d_in[4];
    const float* cstd   = (const float*)d_in[5];
    const float* w_yom  = (const float*)d_in[6];
    const float* w_ylm  = (const float*)d_in[7];
    const float* w_yfm  = (const float*)d_in[8];
    const float* b0_yom = (const float*)d_in[9];
    const float* w1_yom = (const float*)d_in[10];
    const float* b0_ylm = (const float*)d_in[11];
    const float* w2_ylm = (const float*)d_in[12];
    const float* ln_wj  = (const float*)d_in[13];
    const float* rel_bj = (const float*)d_in[14];
    float* out = (float*)d_out;

    int N  = in_sizes[0] / 2;
    int nY = in_sizes[3];

    int L = (N + NCHUNK - 1) / NCHUNK;          // 7 for N=100k
    int nChunks = (N + L - 1) / L;              // 14286
    int gridB = (nChunks + CPB - 1) / CPB;      // 112

    kOne<<<gridB + NSTD, CPB>>>((const float2*)x, y_obs, cmean, cstd,
                                w_yom, w_ylm, w_yfm, b0_yom, w1_yom,
                                b0_ylm, w2_ylm, ln_wj, rel_bj,
                                out, N, nY, L, gridB);
}